// round 10
// baseline (speedup 1.0000x reference)
#include <cuda_runtime.h>
#include <math.h>

typedef unsigned long long ull;

#define BATCH 512
#define CIN   64
#define LIN   1024
#define COUTC 256
#define K1    32
#define STR1  16
#define TT    63
#define NCLS  2
#define KTOT  2048   // CIN*K1

#define ZROWS 66     // dup-z rows: t = -1 .. 64  (row = t+1), each row 512 floats (dup)
#define BSTR  66     // bufA / d1 row stride
#define WSF   6144   // ws staging buffer floats (24KB)

// ---------------- device scratch ----------------
__device__ float g_z1[BATCH * TT * COUTC];       // [n][t][co]
__device__ float g_c2wt[COUTC * 3 * COUTC];      // [(ci*3+k)][2*cog+half]  (co pairs interleaved)
__device__ float g_d1wt[COUTC * COUTC];          // [c][o]
__device__ float g_bn2a[COUTC];

// ---------------- packed fp32x2 helpers ----------------
__device__ __forceinline__ ull pk2(float lo, float hi) {
    ull r; asm("mov.b64 %0, {%1,%2};" : "=l"(r) : "f"(lo), "f"(hi)); return r;
}
__device__ __forceinline__ ull fma2(ull a, ull b, ull c) {
    ull d; asm("fma.rn.f32x2 %0, %1, %2, %3;" : "=l"(d) : "l"(a), "l"(b), "l"(c)); return d;
}
__device__ __forceinline__ float2 upk2(ull v) {
    float2 f; asm("mov.b64 {%0,%1}, %2;" : "=f"(f.x), "=f"(f.y) : "l"(v)); return f;
}

// ---------------- conv1 (im2col GEMM, M=32256 K=2048 N=256) + BN1 ----------------
// (R9 config: at ~95% of the f32x2 RF-bank-limited peak; unchanged)
__global__ __launch_bounds__(128, 2)
void conv1_gemm(const float* __restrict__ x,
                const float* __restrict__ c1w,
                const float* __restrict__ c1b,
                const float* __restrict__ bn1g,
                const float* __restrict__ bn1b,
                const float* __restrict__ bn1m,
                const float* __restrict__ bn1v)
{
    __shared__ __align__(16) float As[2][16][128];
    __shared__ __align__(16) float Bs[2][16][128];
    const int tid  = threadIdx.x;
    const int lane = tid & 31;
    const int w    = tid >> 5;          // 0..3 -> m stripe
    const int mBase = blockIdx.x * 128;
    const int nBase = blockIdx.y * 128;

    const int warp_m = w * 32;
    const int g = lane >> 3;            // 0..3  m-chunk group
    const int j = lane & 7;             // 0..7  n-chunk group

    const int m_row = mBase + tid;
    const int n_idx = m_row / TT;
    const int t_idx = m_row - n_idx * TT;
    const float* xrow = x + ((size_t)n_idx * CIN) * LIN + t_idx * STR1;
    const float* wrow = c1w + (size_t)(nBase + tid) * KTOT;

    ull acc[8][8];
    #pragma unroll
    for (int i = 0; i < 8; i++)
        #pragma unroll
        for (int q = 0; q < 8; q++) acc[i][q] = 0ULL;

    float4 ap0, ap1, ap2, ap3, bq0, bq1, bq2, bq3;

    #define LOAD_REGS(KB) {                                                    \
        const float* abase = xrow + (size_t)((KB) >> 5) * LIN + ((KB) & 31);   \
        ap0 = *(const float4*)(abase);                                         \
        ap1 = *(const float4*)(abase + 4);                                     \
        ap2 = *(const float4*)(abase + 8);                                     \
        ap3 = *(const float4*)(abase + 12);                                    \
        bq0 = *(const float4*)(wrow + (KB));                                   \
        bq1 = *(const float4*)(wrow + (KB) + 4);                               \
        bq2 = *(const float4*)(wrow + (KB) + 8);                               \
        bq3 = *(const float4*)(wrow + (KB) + 12);                              \
    }
    #define STORE_SMEM(B) {                                                    \
        As[B][0][tid]  = ap0.x; As[B][1][tid]  = ap0.y;                        \
        As[B][2][tid]  = ap0.z; As[B][3][tid]  = ap0.w;                        \
        As[B][4][tid]  = ap1.x; As[B][5][tid]  = ap1.y;                        \
        As[B][6][tid]  = ap1.z; As[B][7][tid]  = ap1.w;                        \
        As[B][8][tid]  = ap2.x; As[B][9][tid]  = ap2.y;                        \
        As[B][10][tid] = ap2.z; As[B][11][tid] = ap2.w;                        \
        As[B][12][tid] = ap3.x; As[B][13][tid] = ap3.y;                        \
        As[B][14][tid] = ap3.z; As[B][15][tid] = ap3.w;                        \
        Bs[B][0][tid]  = bq0.x; Bs[B][1][tid]  = bq0.y;                        \
        Bs[B][2][tid]  = bq0.z; Bs[B][3][tid]  = bq0.w;                        \
        Bs[B][4][tid]  = bq1.x; Bs[B][5][tid]  = bq1.y;                        \
        Bs[B][6][tid]  = bq1.z; Bs[B][7][tid]  = bq1.w;                        \
        Bs[B][8][tid]  = bq2.x; Bs[B][9][tid]  = bq2.y;                        \
        Bs[B][10][tid] = bq2.z; Bs[B][11][tid] = bq2.w;                        \
        Bs[B][12][tid] = bq3.x; Bs[B][13][tid] = bq3.y;                        \
        Bs[B][14][tid] = bq3.z; Bs[B][15][tid] = bq3.w;                        \
    }

    LOAD_REGS(0);
    STORE_SMEM(0);
    __syncthreads();

    int buf = 0;
    for (int kb = 0; kb < KTOT; kb += 16) {
        const bool more = (kb + 16) < KTOT;
        if (more) LOAD_REGS(kb + 16);

        const float (*A)[128] = As[buf];
        const float (*B)[128] = Bs[buf];
        #pragma unroll
        for (int kk = 0; kk < 16; kk++) {
            float4 x0 = *(const float4*)&A[kk][warp_m + 4 * g];
            float4 x1 = *(const float4*)&A[kk][warp_m + 16 + 4 * g];
            ulonglong2 n0 = *(const ulonglong2*)&B[kk][4 * j];
            ulonglong2 n1 = *(const ulonglong2*)&B[kk][32 + 4 * j];
            ulonglong2 n2 = *(const ulonglong2*)&B[kk][64 + 4 * j];
            ulonglong2 n3 = *(const ulonglong2*)&B[kk][96 + 4 * j];
            ull ap;
            #define FMA_ROW(I, AV)                        \
                ap = pk2(AV, AV);                         \
                acc[I][0] = fma2(ap, n0.x, acc[I][0]);    \
                acc[I][1] = fma2(ap, n0.y, acc[I][1]);    \
                acc[I][2] = fma2(ap, n1.x, acc[I][2]);    \
                acc[I][3] = fma2(ap, n1.y, acc[I][3]);    \
                acc[I][4] = fma2(ap, n2.x, acc[I][4]);    \
                acc[I][5] = fma2(ap, n2.y, acc[I][5]);    \
                acc[I][6] = fma2(ap, n3.x, acc[I][6]);    \
                acc[I][7] = fma2(ap, n3.y, acc[I][7]);
            FMA_ROW(0, x0.x) FMA_ROW(1, x0.y) FMA_ROW(2, x0.z) FMA_ROW(3, x0.w)
            FMA_ROW(4, x1.x) FMA_ROW(5, x1.y) FMA_ROW(6, x1.z) FMA_ROW(7, x1.w)
            #undef FMA_ROW
        }
        if (more) STORE_SMEM(buf ^ 1);
        __syncthreads();
        buf ^= 1;
    }
    #undef LOAD_REGS
    #undef STORE_SMEM

    float sc[16], bb[16], mm[16], cb[16];
    #pragma unroll
    for (int jj = 0; jj < 16; jj++) {
        int co = nBase + (jj >> 2) * 32 + 4 * j + (jj & 3);
        sc[jj] = bn1g[co] / sqrtf(bn1v[co] + 1e-5f);
        bb[jj] = bn1b[co]; mm[jj] = bn1m[co]; cb[jj] = c1b[co];
    }
    #pragma unroll
    for (int i = 0; i < 8; i++) {
        int m = mBase + warp_m + ((i < 4) ? (4 * g + i) : (16 + 4 * g + i - 4));
        float o_[16];
        #pragma unroll
        for (int q = 0; q < 8; q++) {
            float2 v = upk2(acc[i][q]);
            o_[2 * q] = v.x; o_[2 * q + 1] = v.y;
        }
        #pragma unroll
        for (int jj = 0; jj < 16; jj++) {
            float t1 = (o_[jj] + cb[jj]) - mm[jj];
            o_[jj] = fmaf(t1, sc[jj], bb[jj]);
        }
        float* dst = g_z1 + (size_t)m * COUTC + nBase;
        *(float4*)(dst + 4 * j)      = make_float4(o_[0],  o_[1],  o_[2],  o_[3]);
        *(float4*)(dst + 32 + 4 * j) = make_float4(o_[4],  o_[5],  o_[6],  o_[7]);
        *(float4*)(dst + 64 + 4 * j) = make_float4(o_[8],  o_[9],  o_[10], o_[11]);
        *(float4*)(dst + 96 + 4 * j) = make_float4(o_[12], o_[13], o_[14], o_[15]);
    }
}

// ---------------- prep: conv2/dense1 weight layouts + BN2 scale ----------------
__global__ void prep_kernel(const float* __restrict__ c2w,
                            const float* __restrict__ d1w,
                            const float* __restrict__ bn2g, const float* __restrict__ bn2v)
{
    int i = blockIdx.x * blockDim.x + threadIdx.x;
    if (i < COUTC * 3 * COUTC) {                  // conv2 w: pair-interleaved
        int row = i >> 8, jj = i & 255;
        int ci = row / 3, k = row - 3 * ci;
        int co = (jj >> 1) + 128 * (jj & 1);
        g_c2wt[i] = c2w[(co * COUTC + ci) * 3 + k];
    }
    if (i < COUTC * COUTC) {                      // dense w1: [o][c] -> [c][o]
        int c = i >> 8, o = i & 255;
        g_d1wt[i] = d1w[o * COUTC + c];
    }
    if (i < COUTC) {
        g_bn2a[i] = bn2g[i] / sqrtf(bn2v[i] + 1e-5f);
    }
}

// ---------------- mega kernel ----------------
__global__ __launch_bounds__(512, 1)
void mega_kernel(const float* __restrict__ c2b,
                 const float* __restrict__ bn2b,
                 const float* __restrict__ bn2m,
                 const float* __restrict__ d2w,
                 float* __restrict__ out)
{
    extern __shared__ float sm[];
    float* zin  = sm;                          // dup-z: [row 0..65][512] ; later reused [o][BSTR]
    float* bufA = sm + ZROWS * 2 * COUTC;      // [co][BSTR]
    float* ws   = bufA + COUTC * BSTR;         // 6144-float weight staging (24KB)

    const int n = blockIdx.x;
    const int tid = threadIdx.x;

    // ---- load z1[n] into dup rows 1..63; zero rows 0,64,65 ----
    {
        float4* z4 = (float4*)zin;
        for (int i = tid; i < (2 * COUTC) / 4; i += 512) z4[i] = make_float4(0, 0, 0, 0);
        float4* zp4 = (float4*)(zin + 64 * 2 * COUTC);
        for (int i = tid; i < (4 * COUTC) / 4; i += 512) zp4[i] = make_float4(0, 0, 0, 0);
        const float4* src = (const float4*)(g_z1 + (size_t)n * (TT * COUTC));
        float4* dstv = (float4*)(zin + 2 * COUTC);
        for (int i = tid; i < (TT * COUTC) / 4; i += 512) {
            float4 v = src[i];
            dstv[2 * i]     = make_float4(v.x, v.x, v.y, v.y);
            dstv[2 * i + 1] = make_float4(v.z, v.z, v.w, v.w);
        }
    }

    // ---- conv2 (k=3,p=1) + BN2 : weights staged through smem, 8-ci chunks ----
    {
        const int cog = tid & 127;
        const int th  = tid >> 7;
        const int t0  = th * 16;
        ull acc[16];
        #pragma unroll
        for (int t = 0; t < 16; t++) acc[t] = 0ULL;

        const float* zb = zin + t0 * (2 * COUTC);     // row t0 => t = t0-1
        const float4* gw4 = (const float4*)g_c2wt;    // 1536 float4 per 8-ci chunk
        float4* ws4 = (float4*)ws;
        const ull* wsu = (const ull*)ws;

        // prefetch chunk 0 into regs
        float4 r0 = gw4[tid * 3], r1 = gw4[tid * 3 + 1], r2 = gw4[tid * 3 + 2];
        ws4[tid * 3] = r0; ws4[tid * 3 + 1] = r1; ws4[tid * 3 + 2] = r2;
        __syncthreads();   // also covers the z1 dup-load above

        for (int cc = 0; cc < 32; cc++) {
            if (cc + 1 < 32) {
                int b = (cc + 1) * 1536 + tid * 3;
                r0 = gw4[b]; r1 = gw4[b + 1]; r2 = gw4[b + 2];
            }
            #pragma unroll 2
            for (int cl = 0; cl < 8; cl++) {
                const int ci = cc * 8 + cl;
                ull w0 = wsu[(cl * 3 + 0) * 128 + cog];
                ull w1 = wsu[(cl * 3 + 1) * 128 + cog];
                ull w2 = wsu[(cl * 3 + 2) * 128 + cog];
                ull zz[18];
                #pragma unroll
                for (int jj = 0; jj < 18; jj++)
                    zz[jj] = *(const ull*)(zb + jj * (2 * COUTC) + 2 * ci);
                #pragma unroll
                for (int t = 0; t < 16; t++) {
                    acc[t] = fma2(w0, zz[t],     acc[t]);
                    acc[t] = fma2(w1, zz[t + 1], acc[t]);
                    acc[t] = fma2(w2, zz[t + 2], acc[t]);
                }
            }
            __syncthreads();
            if (cc + 1 < 32) {
                ws4[tid * 3] = r0; ws4[tid * 3 + 1] = r1; ws4[tid * 3 + 2] = r2;
            }
            __syncthreads();
        }

        const int coA = cog, coB = cog + 128;
        const float cbA = c2b[coA], mA = bn2m[coA], sA = g_bn2a[coA], bA = bn2b[coA];
        const float cbB = c2b[coB], mB = bn2m[coB], sB = g_bn2a[coB], bB = bn2b[coB];
        #pragma unroll
        for (int t = 0; t < 16; t++) {
            float2 v = upk2(acc[t]);
            int tt = t0 + t;
            bufA[coA * BSTR + tt] = fmaf((v.x + cbA) - mA, sA, bA);
            bufA[coB * BSTR + tt] = fmaf((v.y + cbB) - mB, sB, bB);
        }
    }
    __syncthreads();

    // ---- encoder CUBA LIF: thr 0.3, cd 0.9, vd 0.9 ----
    if (tid < COUTC) {
        float* row = bufA + tid * BSTR;
        const float cd = (float)(1.0 - 0.9);
        const float vd = (float)(1.0 - 0.9);
        float cur = 0.0f, vol = 0.0f;
        #pragma unroll 1
        for (int t = 0; t < TT; t++) {
            float xv = row[t];
            cur = fmaf(cd, cur, xv);
            vol = fmaf(vd, vol, cur);
            float s = ((vol - 0.3f) >= 0.0f) ? 1.0f : 0.0f;
            row[t] = s;
            vol = vol * (1.0f - s);
        }
        row[TT] = 0.0f;
    }
    __syncthreads();

    // ---- dense1: weights staged through smem, 16-c chunks; t-pair fp32x2 lanes ----
    {
        const int og = tid & 127;
        const int th = tid >> 7;
        const int t0 = th * 16;
        ull a0[8], a1[8];
        #pragma unroll
        for (int p = 0; p < 8; p++) { a0[p] = 0ULL; a1[p] = 0ULL; }

        const float4* gd4 = (const float4*)g_d1wt;    // 1024 float4 per 16-c chunk
        float4* ws4 = (float4*)ws;

        float4 d0 = gd4[tid * 2], d1 = gd4[tid * 2 + 1];
        ws4[tid * 2] = d0; ws4[tid * 2 + 1] = d1;
        __syncthreads();

        for (int ch = 0; ch < 16; ch++) {
            if (ch + 1 < 16) {
                int b = (ch + 1) * 1024 + tid * 2;
                d0 = gd4[b]; d1 = gd4[b + 1];
            }
            #pragma unroll 2
            for (int cl = 0; cl < 16; cl++) {
                const int c = ch * 16 + cl;
                float wa  = ws[cl * 256 + og];
                float wbv = ws[cl * 256 + og + 128];
                ull wap = pk2(wa, wa), wbp = pk2(wbv, wbv);
                const ull* sp = (const ull*)(bufA + c * BSTR + t0);
                #pragma unroll
                for (int p = 0; p < 8; p++) {
                    ull s = sp[p];
                    a0[p] = fma2(wap, s, a0[p]);
                    a1[p] = fma2(wbp, s, a1[p]);
                }
            }
            __syncthreads();
            if (ch + 1 < 16) {
                ws4[tid * 2] = d0; ws4[tid * 2 + 1] = d1;
            }
            __syncthreads();
        }

        ull* o0 = (ull*)(zin + og * BSTR + t0);
        ull* o1 = (ull*)(zin + (og + 128) * BSTR + t0);
        #pragma unroll
        for (int p = 0; p < 8; p++) { o0[p] = a0[p]; o1[p] = a1[p]; }
    }
    __syncthreads();

    // ---- dense1 CUBA LIF: thr 0.1, cd=1, vd=0.1 ----
    if (tid < COUTC) {
        float* row = zin + tid * BSTR;
        const float vdD = (float)(1.0 - 0.1);
        float vol = 0.0f;
        #pragma unroll 1
        for (int t = 0; t < TT; t++) {
            float xv = row[t];
            vol = fmaf(vdD, vol, xv);
            float s = ((vol - 0.1f) >= 0.0f) ? 1.0f : 0.0f;
            row[t] = s;
            vol = vol * (1.0f - s);
        }
    }
    __syncthreads();

    // ---- dense2: [2 x 256] ----
    if (tid < NCLS * TT) {
        int cls = tid / TT, t = tid - cls * TT;
        const float* w = d2w + cls * COUTC;
        float a = 0.0f;
        #pragma unroll 4
        for (int c = 0; c < COUTC; c++) a = fmaf(w[c], zin[c * BSTR + t], a);
        bufA[tid] = a;
    }
    __syncthreads();

    // ---- dense2 CUBA LIF + output ----
    if (tid < NCLS) {
        const float vdD = (float)(1.0 - 0.1);
        float vol = 0.0f;
        const float* rowi = bufA + tid * TT;
        float* rowo = out + (size_t)n * (NCLS * TT) + tid * TT;
        #pragma unroll 1
        for (int t = 0; t < TT; t++) {
            float xv = rowi[t];
            vol = fmaf(vdD, vol, xv);
            float s = ((vol - 0.1f) >= 0.0f) ? 1.0f : 0.0f;
            rowo[t] = s;
            vol = vol * (1.0f - s);
        }
    }
}

// ---------------- launch ----------------
extern "C" void kernel_launch(void* const* d_in, const int* in_sizes, int n_in,
                              void* d_out, int out_size)
{
    const float* x    = (const float*)d_in[0];
    const float* c1w  = (const float*)d_in[1];
    const float* c1b  = (const float*)d_in[2];
    const float* bn1g = (const float*)d_in[3];
    const float* bn1b = (const float*)d_in[4];
    const float* bn1m = (const float*)d_in[5];
    const float* bn1v = (const float*)d_in[6];
    const float* c2w  = (const float*)d_in[7];
    const float* c2b  = (const float*)d_in[8];
    const float* bn2g = (const float*)d_in[9];
    const float* bn2b = (const float*)d_in[10];
    const float* bn2m = (const float*)d_in[11];
    const float* bn2v = (const float*)d_in[12];
    const float* d1w  = (const float*)d_in[13];
    const float* d2w  = (const float*)d_in[14];
    float* out = (float*)d_out;

    const int smem_bytes = (ZROWS * 2 * COUTC + COUTC * BSTR + WSF) * (int)sizeof(float);
    cudaFuncSetAttribute(mega_kernel, cudaFuncAttributeMaxDynamicSharedMemorySize, smem_bytes);

    dim3 g1(252, 2);
    conv1_gemm<<<g1, 128>>>(x, c1w, c1b, bn1g, bn1b, bn1m, bn1v);

    prep_kernel<<<768, 256>>>(c2w, d1w, bn2g, bn2v);

    mega_kernel<<<BATCH, 512, smem_bytes>>>(c2b, bn2b, bn2m, d2w, out);
}

// round 13
// speedup vs baseline: 1.0314x; 1.0314x over previous
#include <cuda_runtime.h>
#include <math.h>

typedef unsigned long long ull;

#define BATCH 512
#define CIN   64
#define LIN   1024
#define COUTC 256
#define K1    32
#define STR1  16
#define TT    63
#define NCLS  2
#define KTOT  2048   // CIN*K1

#define ZROWS 66     // dup-z rows: t = -1 .. 64  (row = t+1), each row 512 floats (dup)
#define BSTR  66     // bufA / d1 row stride

// ---------------- device scratch ----------------
__device__ float g_z1[BATCH * TT * COUTC];       // [n][t][co]
__device__ float g_c2wt[COUTC * 3 * COUTC];      // [(ci*3+k)][2*cog+half]  (co pairs interleaved)
__device__ float g_d1wt[COUTC * COUTC];          // [c][o]
__device__ float g_bn2a[COUTC];

// ---------------- packed fp32x2 helpers ----------------
__device__ __forceinline__ ull pk2(float lo, float hi) {
    ull r; asm("mov.b64 %0, {%1,%2};" : "=l"(r) : "f"(lo), "f"(hi)); return r;
}
__device__ __forceinline__ ull fma2(ull a, ull b, ull c) {
    ull d; asm("fma.rn.f32x2 %0, %1, %2, %3;" : "=l"(d) : "l"(a), "l"(b), "l"(c)); return d;
}
__device__ __forceinline__ float2 upk2(ull v) {
    float2 f; asm("mov.b64 {%0,%1}, %2;" : "=f"(f.x), "=f"(f.y) : "l"(v)); return f;
}

// ---------------- conv1 (im2col GEMM, M=32256 K=2048 N=256) + BN1 + prep fold ----
// Tile 64(M) x 128(N) x 16(K), 128 threads, 3 CTAs/SM, 1008 tiles -> per-SM
// totals {6,7} = 97.4% wave balance (vs 85% at 128-row tiles).
// 4 warps in 2(M)x2(N); warp 32x64; lane grid 4(g)x8(j); micro 8Mx8N in 4-float
// chunks (all LDS.128 contiguous, conflict-free). Ascending-k chain -> bit-exact.
__global__ __launch_bounds__(128, 3)
void conv1_gemm(const float* __restrict__ x,
                const float* __restrict__ c1w,
                const float* __restrict__ c1b,
                const float* __restrict__ bn1g,
                const float* __restrict__ bn1b,
                const float* __restrict__ bn1m,
                const float* __restrict__ bn1v,
                const float* __restrict__ c2w,
                const float* __restrict__ d1w,
                const float* __restrict__ bn2g,
                const float* __restrict__ bn2v)
{
    __shared__ __align__(16) float As[2][16][64];
    __shared__ __align__(16) float Bs[2][16][128];
    const int tid  = threadIdx.x;
    const int lane = tid & 31;
    const int w    = tid >> 5;
    const int mBase = blockIdx.x * 64;
    const int nBase = blockIdx.y * 128;

    // ---- prep fold: y==0 blocks build mega's weight layouts (done before mega runs)
    if (blockIdx.y == 0) {
        int gid = blockIdx.x * 128 + tid;          // 0..64511 over 504 blocks
        for (int i = gid; i < COUTC * 3 * COUTC; i += 504 * 128) {
            int row = i >> 8, jj = i & 255;
            int ci = row / 3, k = row - 3 * ci;
            int co = (jj >> 1) + 128 * (jj & 1);
            g_c2wt[i] = c2w[(co * COUTC + ci) * 3 + k];
        }
        for (int i = gid; i < COUTC * COUTC; i += 504 * 128) {
            int c = i >> 8, o = i & 255;
            g_d1wt[i] = d1w[o * COUTC + c];
        }
        if (gid < COUTC)
            g_bn2a[gid] = bn2g[gid] / sqrtf(bn2v[gid] + 1e-5f);
    }

    const int warp_m = (w & 1) * 32;
    const int warp_n = (w >> 1) * 64;
    const int g = lane >> 3;            // 0..3  m-chunk group
    const int j = lane & 7;             // 0..7  n-chunk group

    // ---- A loader: row am = tid&63, k-half kq = (tid>>6)*8 ----
    const int am = tid & 63;
    const int kq = (tid >> 6) * 8;
    const int m_row = mBase + am;
    const int n_idx = m_row / TT;
    const int t_idx = m_row - n_idx * TT;
    const float* xrow = x + ((size_t)n_idx * CIN) * LIN + t_idx * STR1;
    // ---- B loader: co = tid, 16 consecutive k ----
    const float* wrow = c1w + (size_t)(nBase + tid) * KTOT;

    ull acc[8][4];
    #pragma unroll
    for (int i = 0; i < 8; i++)
        #pragma unroll
        for (int q = 0; q < 4; q++) acc[i][q] = 0ULL;

    float4 ap0, ap1, bq0, bq1, bq2, bq3;

    #define LOAD_REGS(KB) {                                                    \
        int col = (KB) + kq;                                                   \
        const float* abase = xrow + (size_t)(col >> 5) * LIN + (col & 31);     \
        ap0 = *(const float4*)(abase);                                         \
        ap1 = *(const float4*)(abase + 4);                                     \
        bq0 = *(const float4*)(wrow + (KB));                                   \
        bq1 = *(const float4*)(wrow + (KB) + 4);                               \
        bq2 = *(const float4*)(wrow + (KB) + 8);                               \
        bq3 = *(const float4*)(wrow + (KB) + 12);                              \
    }
    #define STORE_SMEM(B) {                                                    \
        As[B][kq + 0][am] = ap0.x; As[B][kq + 1][am] = ap0.y;                  \
        As[B][kq + 2][am] = ap0.z; As[B][kq + 3][am] = ap0.w;                  \
        As[B][kq + 4][am] = ap1.x; As[B][kq + 5][am] = ap1.y;                  \
        As[B][kq + 6][am] = ap1.z; As[B][kq + 7][am] = ap1.w;                  \
        Bs[B][0][tid]  = bq0.x; Bs[B][1][tid]  = bq0.y;                        \
        Bs[B][2][tid]  = bq0.z; Bs[B][3][tid]  = bq0.w;                        \
        Bs[B][4][tid]  = bq1.x; Bs[B][5][tid]  = bq1.y;                        \
        Bs[B][6][tid]  = bq1.z; Bs[B][7][tid]  = bq1.w;                        \
        Bs[B][8][tid]  = bq2.x; Bs[B][9][tid]  = bq2.y;                        \
        Bs[B][10][tid] = bq2.z; Bs[B][11][tid] = bq2.w;                        \
        Bs[B][12][tid] = bq3.x; Bs[B][13][tid] = bq3.y;                        \
        Bs[B][14][tid] = bq3.z; Bs[B][15][tid] = bq3.w;                        \
    }

    LOAD_REGS(0);
    STORE_SMEM(0);
    __syncthreads();

    int buf = 0;
    for (int kb = 0; kb < KTOT; kb += 16) {
        const bool more = (kb + 16) < KTOT;
        if (more) LOAD_REGS(kb + 16);

        const float (*A)[64]  = As[buf];
        const float (*B)[128] = Bs[buf];
        #pragma unroll
        for (int kk = 0; kk < 16; kk++) {
            float4 x0 = *(const float4*)&A[kk][warp_m + 4 * g];           // m 4g..4g+3
            float4 x1 = *(const float4*)&A[kk][warp_m + 16 + 4 * g];      // m 16+4g..
            ulonglong2 n0 = *(const ulonglong2*)&B[kk][warp_n + 4 * j];   // n 4j..4j+3
            ulonglong2 n1 = *(const ulonglong2*)&B[kk][warp_n + 32 + 4 * j];
            ull ap;
            #define FMA_ROW(I, AV)                        \
                ap = pk2(AV, AV);                         \
                acc[I][0] = fma2(ap, n0.x, acc[I][0]);    \
                acc[I][1] = fma2(ap, n0.y, acc[I][1]);    \
                acc[I][2] = fma2(ap, n1.x, acc[I][2]);    \
                acc[I][3] = fma2(ap, n1.y, acc[I][3]);
            FMA_ROW(0, x0.x) FMA_ROW(1, x0.y) FMA_ROW(2, x0.z) FMA_ROW(3, x0.w)
            FMA_ROW(4, x1.x) FMA_ROW(5, x1.y) FMA_ROW(6, x1.z) FMA_ROW(7, x1.w)
            #undef FMA_ROW
        }
        if (more) STORE_SMEM(buf ^ 1);
        __syncthreads();
        buf ^= 1;
    }
    #undef LOAD_REGS
    #undef STORE_SMEM

    // epilogue: ((conv + b) - m) * (g/sqrt(v+eps)) + beta  -> g_z1 [n][t][co]
    float sc[8], bb[8], mm[8], cb[8];
    #pragma unroll
    for (int jj = 0; jj < 8; jj++) {
        int co = nBase + warp_n + ((jj < 4) ? (4 * j + jj) : (32 + 4 * j + jj - 4));
        sc[jj] = bn1g[co] / sqrtf(bn1v[co] + 1e-5f);
        bb[jj] = bn1b[co]; mm[jj] = bn1m[co]; cb[jj] = c1b[co];
    }
    #pragma unroll
    for (int i = 0; i < 8; i++) {
        int m = mBase + warp_m + ((i < 4) ? (4 * g + i) : (16 + 4 * g + i - 4));
        float o_[8];
        #pragma unroll
        for (int q = 0; q < 4; q++) {
            float2 v = upk2(acc[i][q]);
            o_[2 * q] = v.x; o_[2 * q + 1] = v.y;
        }
        #pragma unroll
        for (int jj = 0; jj < 8; jj++) {
            float t1 = (o_[jj] + cb[jj]) - mm[jj];
            o_[jj] = fmaf(t1, sc[jj], bb[jj]);
        }
        float* dst = g_z1 + (size_t)m * COUTC + nBase + warp_n;
        *(float4*)(dst + 4 * j)      = make_float4(o_[0], o_[1], o_[2], o_[3]);
        *(float4*)(dst + 32 + 4 * j) = make_float4(o_[4], o_[5], o_[6], o_[7]);
    }
}

// ---------------- mega kernel (R9 version: register-prefetched weights) ----------
__global__ __launch_bounds__(512, 1)
void mega_kernel(const float* __restrict__ c2b,
                 const float* __restrict__ bn2b,
                 const float* __restrict__ bn2m,
                 const float* __restrict__ d2w,
                 float* __restrict__ out)
{
    extern __shared__ float sm[];
    float* zin  = sm;                          // dup-z: [row 0..65][512] ; later reused [o][BSTR]
    float* bufA = sm + ZROWS * 2 * COUTC;      // [co][BSTR]

    const int n = blockIdx.x;
    const int tid = threadIdx.x;

    // ---- load z1[n] into dup rows 1..63; zero rows 0,64,65 ----
    {
        float4* z4 = (float4*)zin;
        for (int i = tid; i < (2 * COUTC) / 4; i += 512) z4[i] = make_float4(0, 0, 0, 0);
        float4* zp4 = (float4*)(zin + 64 * 2 * COUTC);
        for (int i = tid; i < (4 * COUTC) / 4; i += 512) zp4[i] = make_float4(0, 0, 0, 0);
        const float4* src = (const float4*)(g_z1 + (size_t)n * (TT * COUTC));
        float4* dstv = (float4*)(zin + 2 * COUTC);
        for (int i = tid; i < (TT * COUTC) / 4; i += 512) {
            float4 v = src[i];
            dstv[2 * i]     = make_float4(v.x, v.x, v.y, v.y);
            dstv[2 * i + 1] = make_float4(v.z, v.z, v.w, v.w);
        }
    }
    __syncthreads();

    // ---- conv2 (k=3,p=1) + BN2 : fp32x2 lanes = (co, co+128), prefetched weights ----
    {
        const int cog = tid & 127;
        const int th  = tid >> 7;
        const int t0  = th * 16;
        ull acc[16];
        #pragma unroll
        for (int t = 0; t < 16; t++) acc[t] = 0ULL;

        const float* zb = zin + t0 * (2 * COUTC);     // row t0 => t = t0-1
        const ull* wb = (const ull*)g_c2wt;

        ull w0 = wb[cog], w1 = wb[128 + cog], w2 = wb[256 + cog];
        #pragma unroll 2
        for (int ci = 0; ci < COUTC; ci++) {
            const int cin = (ci + 1) & 255;
            const ull* wn = wb + cin * 384;
            ull nw0 = wn[cog], nw1 = wn[128 + cog], nw2 = wn[256 + cog];

            ull zz[18];
            #pragma unroll
            for (int jj = 0; jj < 18; jj++)
                zz[jj] = *(const ull*)(zb + jj * (2 * COUTC) + 2 * ci);
            #pragma unroll
            for (int t = 0; t < 16; t++) {
                acc[t] = fma2(w0, zz[t],     acc[t]);
                acc[t] = fma2(w1, zz[t + 1], acc[t]);
                acc[t] = fma2(w2, zz[t + 2], acc[t]);
            }
            w0 = nw0; w1 = nw1; w2 = nw2;
        }
        const int coA = cog, coB = cog + 128;
        const float cbA = c2b[coA], mA = bn2m[coA], sA = g_bn2a[coA], bA = bn2b[coA];
        const float cbB = c2b[coB], mB = bn2m[coB], sB = g_bn2a[coB], bB = bn2b[coB];
        #pragma unroll
        for (int t = 0; t < 16; t++) {
            float2 v = upk2(acc[t]);
            int tt = t0 + t;
            bufA[coA * BSTR + tt] = fmaf((v.x + cbA) - mA, sA, bA);
            bufA[coB * BSTR + tt] = fmaf((v.y + cbB) - mB, sB, bB);
        }
    }
    __syncthreads();

    // ---- encoder CUBA LIF: thr 0.3, cd 0.9, vd 0.9 ----
    if (tid < COUTC) {
        float* row = bufA + tid * BSTR;
        const float cd = (float)(1.0 - 0.9);
        const float vd = (float)(1.0 - 0.9);
        float cur = 0.0f, vol = 0.0f;
        #pragma unroll 1
        for (int t = 0; t < TT; t++) {
            float xv = row[t];
            cur = fmaf(cd, cur, xv);
            vol = fmaf(vd, vol, cur);
            float s = ((vol - 0.3f) >= 0.0f) ? 1.0f : 0.0f;
            row[t] = s;
            vol = vol * (1.0f - s);
        }
        row[TT] = 0.0f;
    }
    __syncthreads();

    // ---- dense1: fp32x2 lanes = t-pairs, prefetched weights ----
    {
        const int og = tid & 127;
        const int th = tid >> 7;
        const int t0 = th * 16;
        ull a0[8], a1[8];
        #pragma unroll
        for (int p = 0; p < 8; p++) { a0[p] = 0ULL; a1[p] = 0ULL; }

        float wa = g_d1wt[og], wbv = g_d1wt[og + 128];
        #pragma unroll 2
        for (int c = 0; c < COUTC; c++) {
            const int cn = (c + 1) & 255;
            float nwa = g_d1wt[cn * COUTC + og];
            float nwb = g_d1wt[cn * COUTC + og + 128];

            ull wap = pk2(wa, wa), wbp = pk2(wbv, wbv);
            const ull* sp = (const ull*)(bufA + c * BSTR + t0);
            #pragma unroll
            for (int p = 0; p < 8; p++) {
                ull s = sp[p];
                a0[p] = fma2(wap, s, a0[p]);
                a1[p] = fma2(wbp, s, a1[p]);
            }
            wa = nwa; wbv = nwb;
        }
        ull* d0 = (ull*)(zin + og * BSTR + t0);
        ull* d1 = (ull*)(zin + (og + 128) * BSTR + t0);
        #pragma unroll
        for (int p = 0; p < 8; p++) { d0[p] = a0[p]; d1[p] = a1[p]; }
    }
    __syncthreads();

    // ---- dense1 CUBA LIF: thr 0.1, cd=1, vd=0.1 ----
    if (tid < COUTC) {
        float* row = zin + tid * BSTR;
        const float vdD = (float)(1.0 - 0.1);
        float vol = 0.0f;
        #pragma unroll 1
        for (int t = 0; t < TT; t++) {
            float xv = row[t];
            vol = fmaf(vdD, vol, xv);
            float s = ((vol - 0.1f) >= 0.0f) ? 1.0f : 0.0f;
            row[t] = s;
            vol = vol * (1.0f - s);
        }
    }
    __syncthreads();

    // ---- dense2: [2 x 256] ----
    if (tid < NCLS * TT) {
        int cls = tid / TT, t = tid - cls * TT;
        const float* w = d2w + cls * COUTC;
        float a = 0.0f;
        #pragma unroll 4
        for (int c = 0; c < COUTC; c++) a = fmaf(w[c], zin[c * BSTR + t], a);
        bufA[tid] = a;
    }
    __syncthreads();

    // ---- dense2 CUBA LIF + output ----
    if (tid < NCLS) {
        const float vdD = (float)(1.0 - 0.1);
        float vol = 0.0f;
        const float* rowi = bufA + tid * TT;
        float* rowo = out + (size_t)n * (NCLS * TT) + tid * TT;
        #pragma unroll 1
        for (int t = 0; t < TT; t++) {
            float xv = rowi[t];
            vol = fmaf(vdD, vol, xv);
            float s = ((vol - 0.1f) >= 0.0f) ? 1.0f : 0.0f;
            rowo[t] = s;
            vol = vol * (1.0f - s);
        }
    }
}

// ---------------- launch ----------------
extern "C" void kernel_launch(void* const* d_in, const int* in_sizes, int n_in,
                              void* d_out, int out_size)
{
    const float* x    = (const float*)d_in[0];
    const float* c1w  = (const float*)d_in[1];
    const float* c1b  = (const float*)d_in[2];
    const float* bn1g = (const float*)d_in[3];
    const float* bn1b = (const float*)d_in[4];
    const float* bn1m = (const float*)d_in[5];
    const float* bn1v = (const float*)d_in[6];
    const float* c2w  = (const float*)d_in[7];
    const float* c2b  = (const float*)d_in[8];
    const float* bn2g = (const float*)d_in[9];
    const float* bn2b = (const float*)d_in[10];
    const float* bn2m = (const float*)d_in[11];
    const float* bn2v = (const float*)d_in[12];
    const float* d1w  = (const float*)d_in[13];
    const float* d2w  = (const float*)d_in[14];
    float* out = (float*)d_out;

    const int smem_bytes = (ZROWS * 2 * COUTC + COUTC * BSTR) * (int)sizeof(float);
    cudaFuncSetAttribute(mega_kernel, cudaFuncAttributeMaxDynamicSharedMemorySize, smem_bytes);

    // conv1 (with prep folded into blockIdx.y==0 blocks); mega after it completes
    dim3 g1(504, 2);
    conv1_gemm<<<g1, 128>>>(x, c1w, c1b, bn1g, bn1b, bn1m, bn1v,
                            c2w, d1w, bn2g, bn2v);

    mega_kernel<<<BATCH, 512, smem_bytes>>>(c2b, bn2b, bn2m, d2w, out);
}

// round 15
// speedup vs baseline: 1.0631x; 1.0307x over previous
#include <cuda_runtime.h>
#include <math.h>

typedef unsigned long long ull;

#define BATCH 512
#define CIN   64
#define LIN   1024
#define COUTC 256
#define K1    32
#define STR1  16
#define TT    63
#define NCLS  2
#define KTOT  2048   // CIN*K1

#define ZTW  68      // transposed-z row width (floats): t=-1..64 pad, 16B-aligned rows
#define BSTR 66      // act/spike row stride in smem

// ---------------- device scratch ----------------
__device__ float g_z1[BATCH * TT * COUTC];        // [n][t][co]
__device__ float g_spk[BATCH * COUTC * 64];       // encoder spikes [n][co][64] (t=63 zero)
__device__ float g_d1s[BATCH * COUTC * 64];       // dense1 spikes  [n][o][64]  (t=63 zero)
__device__ float g_c2wt[COUTC * 3 * COUTC];       // [(ci*3+k)][2*p+h] pairs (p, p+128)
__device__ float g_d1wt[COUTC * COUTC];           // [c][o]
__device__ float g_bn2a[COUTC];

// ---------------- packed fp32x2 helpers ----------------
__device__ __forceinline__ ull pk2(float lo, float hi) {
    ull r; asm("mov.b64 %0, {%1,%2};" : "=l"(r) : "f"(lo), "f"(hi)); return r;
}
__device__ __forceinline__ ull fma2(ull a, ull b, ull c) {
    ull d; asm("fma.rn.f32x2 %0, %1, %2, %3;" : "=l"(d) : "l"(a), "l"(b), "l"(c)); return d;
}
__device__ __forceinline__ float2 upk2(ull v) {
    float2 f; asm("mov.b64 {%0,%1}, %2;" : "=f"(f.x), "=f"(f.y) : "l"(v)); return f;
}

// ---------------- conv1 (im2col GEMM) + BN1 + prep fold (R13, at fma2 floor) ----
__global__ __launch_bounds__(128, 3)
void conv1_gemm(const float* __restrict__ x,
                const float* __restrict__ c1w,
                const float* __restrict__ c1b,
                const float* __restrict__ bn1g,
                const float* __restrict__ bn1b,
                const float* __restrict__ bn1m,
                const float* __restrict__ bn1v,
                const float* __restrict__ c2w,
                const float* __restrict__ d1w,
                const float* __restrict__ bn2g,
                const float* __restrict__ bn2v)
{
    __shared__ __align__(16) float As[2][16][64];
    __shared__ __align__(16) float Bs[2][16][128];
    const int tid  = threadIdx.x;
    const int lane = tid & 31;
    const int w    = tid >> 5;
    const int mBase = blockIdx.x * 64;
    const int nBase = blockIdx.y * 128;

    if (blockIdx.y == 0) {
        int gid = blockIdx.x * 128 + tid;
        for (int i = gid; i < COUTC * 3 * COUTC; i += 504 * 128) {
            int row = i >> 8, jj = i & 255;
            int ci = row / 3, k = row - 3 * ci;
            int co = (jj >> 1) + 128 * (jj & 1);
            g_c2wt[i] = c2w[(co * COUTC + ci) * 3 + k];
        }
        for (int i = gid; i < COUTC * COUTC; i += 504 * 128) {
            int c = i >> 8, o = i & 255;
            g_d1wt[i] = d1w[o * COUTC + c];
        }
        if (gid < COUTC)
            g_bn2a[gid] = bn2g[gid] / sqrtf(bn2v[gid] + 1e-5f);
    }

    const int warp_m = (w & 1) * 32;
    const int warp_n = (w >> 1) * 64;
    const int g = lane >> 3;
    const int j = lane & 7;

    const int am = tid & 63;
    const int kq = (tid >> 6) * 8;
    const int m_row = mBase + am;
    const int n_idx = m_row / TT;
    const int t_idx = m_row - n_idx * TT;
    const float* xrow = x + ((size_t)n_idx * CIN) * LIN + t_idx * STR1;
    const float* wrow = c1w + (size_t)(nBase + tid) * KTOT;

    ull acc[8][4];
    #pragma unroll
    for (int i = 0; i < 8; i++)
        #pragma unroll
        for (int q = 0; q < 4; q++) acc[i][q] = 0ULL;

    float4 ap0, ap1, bq0, bq1, bq2, bq3;

    #define LOAD_REGS(KB) {                                                    \
        int col = (KB) + kq;                                                   \
        const float* abase = xrow + (size_t)(col >> 5) * LIN + (col & 31);     \
        ap0 = *(const float4*)(abase);                                         \
        ap1 = *(const float4*)(abase + 4);                                     \
        bq0 = *(const float4*)(wrow + (KB));                                   \
        bq1 = *(const float4*)(wrow + (KB) + 4);                               \
        bq2 = *(const float4*)(wrow + (KB) + 8);                               \
        bq3 = *(const float4*)(wrow + (KB) + 12);                              \
    }
    #define STORE_SMEM(B) {                                                    \
        As[B][kq + 0][am] = ap0.x; As[B][kq + 1][am] = ap0.y;                  \
        As[B][kq + 2][am] = ap0.z; As[B][kq + 3][am] = ap0.w;                  \
        As[B][kq + 4][am] = ap1.x; As[B][kq + 5][am] = ap1.y;                  \
        As[B][kq + 6][am] = ap1.z; As[B][kq + 7][am] = ap1.w;                  \
        Bs[B][0][tid]  = bq0.x; Bs[B][1][tid]  = bq0.y;                        \
        Bs[B][2][tid]  = bq0.z; Bs[B][3][tid]  = bq0.w;                        \
        Bs[B][4][tid]  = bq1.x; Bs[B][5][tid]  = bq1.y;                        \
        Bs[B][6][tid]  = bq1.z; Bs[B][7][tid]  = bq1.w;                        \
        Bs[B][8][tid]  = bq2.x; Bs[B][9][tid]  = bq2.y;                        \
        Bs[B][10][tid] = bq2.z; Bs[B][11][tid] = bq2.w;                        \
        Bs[B][12][tid] = bq3.x; Bs[B][13][tid] = bq3.y;                        \
        Bs[B][14][tid] = bq3.z; Bs[B][15][tid] = bq3.w;                        \
    }

    LOAD_REGS(0);
    STORE_SMEM(0);
    __syncthreads();

    int buf = 0;
    for (int kb = 0; kb < KTOT; kb += 16) {
        const bool more = (kb + 16) < KTOT;
        if (more) LOAD_REGS(kb + 16);

        const float (*A)[64]  = As[buf];
        const float (*B)[128] = Bs[buf];
        #pragma unroll
        for (int kk = 0; kk < 16; kk++) {
            float4 x0 = *(const float4*)&A[kk][warp_m + 4 * g];
            float4 x1 = *(const float4*)&A[kk][warp_m + 16 + 4 * g];
            ulonglong2 n0 = *(const ulonglong2*)&B[kk][warp_n + 4 * j];
            ulonglong2 n1 = *(const ulonglong2*)&B[kk][warp_n + 32 + 4 * j];
            ull ap;
            #define FMA_ROW(I, AV)                        \
                ap = pk2(AV, AV);                         \
                acc[I][0] = fma2(ap, n0.x, acc[I][0]);    \
                acc[I][1] = fma2(ap, n0.y, acc[I][1]);    \
                acc[I][2] = fma2(ap, n1.x, acc[I][2]);    \
                acc[I][3] = fma2(ap, n1.y, acc[I][3]);
            FMA_ROW(0, x0.x) FMA_ROW(1, x0.y) FMA_ROW(2, x0.z) FMA_ROW(3, x0.w)
            FMA_ROW(4, x1.x) FMA_ROW(5, x1.y) FMA_ROW(6, x1.z) FMA_ROW(7, x1.w)
            #undef FMA_ROW
        }
        if (more) STORE_SMEM(buf ^ 1);
        __syncthreads();
        buf ^= 1;
    }
    #undef LOAD_REGS
    #undef STORE_SMEM

    float sc[8], bb[8], mm[8], cb[8];
    #pragma unroll
    for (int jj = 0; jj < 8; jj++) {
        int co = nBase + warp_n + ((jj < 4) ? (4 * j + jj) : (32 + 4 * j + jj - 4));
        sc[jj] = bn1g[co] / sqrtf(bn1v[co] + 1e-5f);
        bb[jj] = bn1b[co]; mm[jj] = bn1m[co]; cb[jj] = c1b[co];
    }
    #pragma unroll
    for (int i = 0; i < 8; i++) {
        int m = mBase + warp_m + ((i < 4) ? (4 * g + i) : (16 + 4 * g + i - 4));
        float o_[8];
        #pragma unroll
        for (int q = 0; q < 4; q++) {
            float2 v = upk2(acc[i][q]);
            o_[2 * q] = v.x; o_[2 * q + 1] = v.y;
        }
        #pragma unroll
        for (int jj = 0; jj < 8; jj++) {
            float t1 = (o_[jj] + cb[jj]) - mm[jj];
            o_[jj] = fmaf(t1, sc[jj], bb[jj]);
        }
        float* dst = g_z1 + (size_t)m * COUTC + nBase + warp_n;
        *(float4*)(dst + 4 * j)      = make_float4(o_[0], o_[1], o_[2], o_[3]);
        *(float4*)(dst + 32 + 4 * j) = make_float4(o_[4], o_[5], o_[6], o_[7]);
    }
}

// ---------------- conv2 + BN2 + encoder LIF : grid (n, co-half), 2 CTA/SM -------
__global__ __launch_bounds__(256, 2)
void conv2lif_kernel(const float* __restrict__ c2b,
                     const float* __restrict__ bn2b,
                     const float* __restrict__ bn2m)
{
    extern __shared__ float sm[];
    float* zt   = sm;                   // transposed z: [ci][ZTW], float idx = t+1
    float* bufA = sm + COUTC * ZTW;     // [128][BSTR]

    const int n    = blockIdx.x;
    const int half = blockIdx.y;
    const int tid  = threadIdx.x;
    const int cog  = tid & 63;
    const int th   = tid >> 6;          // 0..3
    const int t0   = th * 16;
    const int p    = half * 64 + cog;   // weight pair index (co=p, co=p+128)

    // ---- zero + fill transposed z (thread = ci, walks t; gmem coalesced) ----
    {
        float4* z4 = (float4*)zt;
        for (int i = tid; i < COUTC * ZTW / 4; i += 256) z4[i] = make_float4(0, 0, 0, 0);
        __syncthreads();
        const float* src = g_z1 + (size_t)n * (TT * COUTC) + tid;
        float* dst = zt + tid * ZTW + 1;
        #pragma unroll 7
        for (int t = 0; t < TT; t++) dst[t] = src[t * COUTC];
    }
    __syncthreads();

    // ---- conv2: fp32x2 lanes = (co, co+128); z via 4xLDS.128+LDS.64 broadcast ----
    ull acc[16];
    #pragma unroll
    for (int t = 0; t < 16; t++) acc[t] = 0ULL;
    {
        const ull* wb = (const ull*)g_c2wt;
        ull w0 = wb[p], w1 = wb[128 + p], w2 = wb[256 + p];
        #pragma unroll 2
        for (int ci = 0; ci < COUTC; ci++) {
            const int cin = (ci + 1) & 255;
            const ull* wn = wb + cin * 384;
            ull nw0 = wn[p], nw1 = wn[128 + p], nw2 = wn[256 + p];

            const float* zb = zt + ci * ZTW + t0;     // float idx t0+j == t0-1+j (+1)
            float4 f0 = *(const float4*)(zb);
            float4 f1 = *(const float4*)(zb + 4);
            float4 f2 = *(const float4*)(zb + 8);
            float4 f3 = *(const float4*)(zb + 12);
            float2 f4 = *(const float2*)(zb + 16);
            float zr[18] = {f0.x, f0.y, f0.z, f0.w, f1.x, f1.y, f1.z, f1.w,
                            f2.x, f2.y, f2.z, f2.w, f3.x, f3.y, f3.z, f3.w,
                            f4.x, f4.y};
            ull zz[18];
            #pragma unroll
            for (int jj = 0; jj < 18; jj++) zz[jj] = pk2(zr[jj], zr[jj]);
            #pragma unroll
            for (int t = 0; t < 16; t++) {
                acc[t] = fma2(w0, zz[t],     acc[t]);
                acc[t] = fma2(w1, zz[t + 1], acc[t]);
                acc[t] = fma2(w2, zz[t + 2], acc[t]);
            }
            w0 = nw0; w1 = nw1; w2 = nw2;
        }
    }
    // ---- BN2 epilogue into bufA (local rows: cog -> coA, 64+cog -> coB) ----
    {
        const int coA = half * 64 + cog, coB = coA + 128;
        const float cbA = c2b[coA], mA = bn2m[coA], sA = g_bn2a[coA], bA = bn2b[coA];
        const float cbB = c2b[coB], mB = bn2m[coB], sB = g_bn2a[coB], bB = bn2b[coB];
        #pragma unroll
        for (int t = 0; t < 16; t++) {
            float2 v = upk2(acc[t]);
            int tt = t0 + t;                    // tt=63 dummy, zeroed after LIF
            bufA[cog * BSTR + tt]        = fmaf((v.x + cbA) - mA, sA, bA);
            bufA[(64 + cog) * BSTR + tt] = fmaf((v.y + cbB) - mB, sB, bB);
        }
    }
    __syncthreads();

    // ---- encoder CUBA LIF (128 rows, per-co independent) ----
    if (tid < 128) {
        float* row = bufA + tid * BSTR;
        const float cd = (float)(1.0 - 0.9);
        const float vd = (float)(1.0 - 0.9);
        float cur = 0.0f, vol = 0.0f;
        #pragma unroll 1
        for (int t = 0; t < TT; t++) {
            float xv = row[t];
            cur = fmaf(cd, cur, xv);
            vol = fmaf(vd, vol, cur);
            float s = ((vol - 0.3f) >= 0.0f) ? 1.0f : 0.0f;
            row[t] = s;
            vol = vol * (1.0f - s);
        }
        row[TT] = 0.0f;
    }
    __syncthreads();

    // ---- copy spikes to gmem [n][co][64] ----
    for (int idx = tid; idx < 128 * 64; idx += 256) {
        int r = idx >> 6, t = idx & 63;
        int co = (r < 64) ? (half * 64 + r) : (128 + half * 64 + (r - 64));
        g_spk[((size_t)n * COUTC + co) * 64 + t] = bufA[r * BSTR + t];
    }
}

// ---------------- dense1 + LIF : grid (n, o-half), 2 CTA/SM --------------------
__global__ __launch_bounds__(256, 2)
void dense1lif_kernel()
{
    extern __shared__ float sm[];
    float* spk  = sm;                   // [256][BSTR]
    float* d1sm = sm + COUTC * BSTR;    // [128][BSTR]

    const int n    = blockIdx.x;
    const int half = blockIdx.y;
    const int tid  = threadIdx.x;

    // ---- load spikes (t=63 already zero in gmem) ----
    for (int idx = tid; idx < COUTC * 64; idx += 256) {
        int c = idx >> 6, t = idx & 63;
        spk[c * BSTR + t] = g_spk[(size_t)n * COUTC * 64 + idx];
    }
    __syncthreads();

    // ---- dense1: thread (og, th) -> o = half*128+og, t in [th*32, th*32+32) ----
    {
        const int og = tid & 127;
        const int th = tid >> 7;
        const int t0 = th * 32;
        const int o  = half * 128 + og;
        ull a[16];
        #pragma unroll
        for (int pq = 0; pq < 16; pq++) a[pq] = 0ULL;

        float w = g_d1wt[o];
        #pragma unroll 2
        for (int c = 0; c < COUTC; c++) {
            const int cn = (c + 1) & 255;
            float nw = g_d1wt[cn * COUTC + o];
            ull wp = pk2(w, w);
            const ull* sp = (const ull*)(spk + c * BSTR + t0);
            #pragma unroll
            for (int pq = 0; pq < 16; pq++)
                a[pq] = fma2(wp, sp[pq], a[pq]);
            w = nw;
        }
        ull* dd = (ull*)(d1sm + og * BSTR + t0);
        #pragma unroll
        for (int pq = 0; pq < 16; pq++) dd[pq] = a[pq];
    }
    __syncthreads();

    // ---- dense1 CUBA LIF (128 rows) ----
    if (tid < 128) {
        float* row = d1sm + tid * BSTR;
        const float vdD = (float)(1.0 - 0.1);
        float vol = 0.0f;
        #pragma unroll 1
        for (int t = 0; t < TT; t++) {
            float xv = row[t];
            vol = fmaf(vdD, vol, xv);
            float s = ((vol - 0.1f) >= 0.0f) ? 1.0f : 0.0f;
            row[t] = s;
            vol = vol * (1.0f - s);
        }
        row[TT] = 0.0f;
    }
    __syncthreads();

    for (int idx = tid; idx < 128 * 64; idx += 256) {
        int r = idx >> 6, t = idx & 63;
        g_d1s[((size_t)n * COUTC + half * 128 + r) * 64 + t] = d1sm[r * BSTR + t];
    }
}

// ---------------- dense2 + LIF + output : grid n, 128 thr ----------------------
__global__ __launch_bounds__(128, 3)
void dense2_kernel(const float* __restrict__ d2w, float* __restrict__ out)
{
    extern __shared__ float sm[];
    float* spk = sm;                    // [256][64]
    float* d2b = sm + COUTC * 64;       // [2][63]

    const int n = blockIdx.x;
    const int tid = threadIdx.x;

    {
        const float4* src = (const float4*)(g_d1s + (size_t)n * COUTC * 64);
        float4* dst = (float4*)spk;
        for (int i = tid; i < COUTC * 64 / 4; i += 128) dst[i] = src[i];
    }
    __syncthreads();

    if (tid < NCLS * TT) {
        int cls = tid / TT, t = tid - cls * TT;
        const float* w = d2w + cls * COUTC;
        float a = 0.0f;
        #pragma unroll 4
        for (int c = 0; c < COUTC; c++) a = fmaf(w[c], spk[c * 64 + t], a);
        d2b[tid] = a;
    }
    __syncthreads();

    if (tid < NCLS) {
        const float vdD = (float)(1.0 - 0.1);
        float vol = 0.0f;
        const float* rowi = d2b + tid * TT;
        float* rowo = out + (size_t)n * (NCLS * TT) + tid * TT;
        #pragma unroll 1
        for (int t = 0; t < TT; t++) {
            float xv = rowi[t];
            vol = fmaf(vdD, vol, xv);
            float s = ((vol - 0.1f) >= 0.0f) ? 1.0f : 0.0f;
            rowo[t] = s;
            vol = vol * (1.0f - s);
        }
    }
}

// ---------------- launch ----------------
extern "C" void kernel_launch(void* const* d_in, const int* in_sizes, int n_in,
                              void* d_out, int out_size)
{
    const float* x    = (const float*)d_in[0];
    const float* c1w  = (const float*)d_in[1];
    const float* c1b  = (const float*)d_in[2];
    const float* bn1g = (const float*)d_in[3];
    const float* bn1b = (const float*)d_in[4];
    const float* bn1m = (const float*)d_in[5];
    const float* bn1v = (const float*)d_in[6];
    const float* c2w  = (const float*)d_in[7];
    const float* c2b  = (const float*)d_in[8];
    const float* bn2g = (const float*)d_in[9];
    const float* bn2b = (const float*)d_in[10];
    const float* bn2m = (const float*)d_in[11];
    const float* bn2v = (const float*)d_in[12];
    const float* d1w  = (const float*)d_in[13];
    const float* d2w  = (const float*)d_in[14];
    float* out = (float*)d_out;

    const int smemA = (COUTC * ZTW + 128 * BSTR) * (int)sizeof(float);   // 103.4 KB
    const int smemB = (COUTC * BSTR + 128 * BSTR) * (int)sizeof(float);  // 101.4 KB
    const int smemC = (COUTC * 64 + 128) * (int)sizeof(float);           // 66.0 KB
    cudaFuncSetAttribute(conv2lif_kernel, cudaFuncAttributeMaxDynamicSharedMemorySize, smemA);
    cudaFuncSetAttribute(dense1lif_kernel, cudaFuncAttributeMaxDynamicSharedMemorySize, smemB);
    cudaFuncSetAttribute(dense2_kernel, cudaFuncAttributeMaxDynamicSharedMemorySize, smemC);

    dim3 g1(504, 2);
    conv1_gemm<<<g1, 128>>>(x, c1w, c1b, bn1g, bn1b, bn1m, bn1v,
                            c2w, d1w, bn2g, bn2v);

    dim3 g2(BATCH, 2);
    conv2lif_kernel<<<g2, 256, smemA>>>(c2b, bn2b, bn2m);

    dense1lif_kernel<<<g2, 256, smemB>>>();

    dense2_kernel<<<BATCH, 128, smemC>>>(d2w, out);
}